// round 17
// baseline (speedup 1.0000x reference)
#include <cuda_runtime.h>
#include <cuda_fp16.h>

#define BB 2
#define LL 384
#define HH 8
#define DD 64
#define HIDN 512
#define BH (BB*HH)          // 16
#define MROWS (BB*LL)       // 768
#define X_ELEMS (MROWS*HIDN)    // 393216
#define A_ELEMS (BH*LL*LL)      // 2359296
#define FD 128              // feature dim (2 segments x 64)

// -------- scratch (no dynamic allocation allowed) --------
__device__ __half g_Qh [X_ELEMS];   // query -> half
__device__ __half g_Kh2[X_ELEMS];   // key   -> half
__device__ __half g_Vin[X_ELEMS];   // value -> half
__device__ __half g_Wvh[HIDN*HIDN];
__device__ __half g_Woh[HIDN*HIDN];
__device__ __half g_Wfqh[HIDN*HIDN];  // fused W1@Wq per head, half
__device__ __half g_Wfkh[HIDN*HIDN];  // fused W2@Wk per head, half
__device__ float  g_bfq[HIDN];
__device__ float  g_bfk[HIDN];
__device__ __half g_FQ[BH*LL*FD];   // [bh][l][128]
__device__ __half g_FK[BH*LL*FD];   // [bh][l][128]
__device__ __half g_Vh[BH*DD*LL];   // [bh][d][l]
__device__ float  g_ck[BH*LL];
__device__ __half g_Xh[X_ELEMS];    // AV output, half
__device__ float  g_attn[A_ELEMS];

__device__ __forceinline__ float tanh_ap(float x) {
    float y; asm("tanh.approx.f32 %0, %1;" : "=f"(y) : "f"(x)); return y;
}
__device__ __forceinline__ void mma_f16(float* c, const unsigned* a, const unsigned* b) {
    asm volatile(
        "mma.sync.aligned.m16n8k16.row.col.f32.f16.f16.f32 "
        "{%0,%1,%2,%3}, {%4,%5,%6,%7}, {%8,%9}, {%0,%1,%2,%3};"
        : "+f"(c[0]), "+f"(c[1]), "+f"(c[2]), "+f"(c[3])
        : "r"(a[0]), "r"(a[1]), "r"(a[2]), "r"(a[3]), "r"(b[0]), "r"(b[1]));
}
__device__ __forceinline__ unsigned h2u(__half2 v) { return *(unsigned*)&v; }

// ---------------- one-shot fp32 -> f16 conversion of inputs/weights ----------------
__global__ void __launch_bounds__(256) cvt_half_k(
    const float* __restrict__ q, const float* __restrict__ k, const float* __restrict__ v,
    const float* __restrict__ wv, const float* __restrict__ wo)
{
    int z = blockIdx.y;
    const float* src; __half* dst; int n;
    if      (z == 0) { src = q;  dst = g_Qh;  n = X_ELEMS; }
    else if (z == 1) { src = k;  dst = g_Kh2; n = X_ELEMS; }
    else if (z == 2) { src = v;  dst = g_Vin; n = X_ELEMS; }
    else if (z == 3) { src = wv; dst = g_Wvh; n = HIDN*HIDN; }
    else             { src = wo; dst = g_Woh; n = HIDN*HIDN; }
    int idx = blockIdx.x * 256 + threadIdx.x;   // one float4
    if (idx * 4 < n) {
        float4 f = *(const float4*)&src[idx * 4];
        __half2 lo = __floats2half2_rn(f.x, f.y);
        __half2 hi = __floats2half2_rn(f.z, f.w);
        *(unsigned*)&dst[idx * 4]     = h2u(lo);
        *(unsigned*)&dst[idx * 4 + 2] = h2u(hi);
    }
}

// ---------------- prep: fused per-head weights (half output) ----------------
__global__ void __launch_bounds__(256) prep_fuse(
    const float* __restrict__ W1, const float* __restrict__ b1,
    const float* __restrict__ W2, const float* __restrict__ b2,
    const float* __restrict__ Wq, const float* __restrict__ bq,
    const float* __restrict__ Wk, const float* __restrict__ bk)
{
    int h   = blockIdx.x;
    int sel = blockIdx.y;
    int c0  = blockIdx.z * 64;
    const float* Wh   = sel ? W2 : W1;
    const float* bh_  = sel ? b2 : b1;
    const float* Wsrc = sel ? Wk : Wq;
    const float* bsrc = sel ? bk : bq;
    __half* Wout = sel ? g_Wfkh : g_Wfqh;
    float*  bout = sel ? g_bfk  : g_bfq;
    __shared__ float Ws[DD][DD + 1];
    __shared__ float Ts[DD][DD + 1];
    int tid = threadIdx.x;
    for (int t = tid; t < DD * DD; t += 256) {
        Ws[t >> 6][t & 63] = Wh[t];
        Ts[t >> 6][t & 63] = Wsrc[(h * DD + (t >> 6)) * HIDN + c0 + (t & 63)];
    }
    __syncthreads();
    if (blockIdx.z == 0 && tid < DD) {
        float acc = bh_[tid];
        for (int j = 0; j < DD; j++) acc += Ws[tid][j] * bsrc[h * DD + j];
        bout[h * DD + tid] = acc;
    }
    int i = tid & 63;
    int g = tid >> 6;
#pragma unroll
    for (int cc = 0; cc < 16; cc++) {
        int c = g * 16 + cc;
        float acc = 0.f;
#pragma unroll 8
        for (int j = 0; j < DD; j++) acc = fmaf(Ws[i][j], Ts[j][c], acc);
        Wout[(h * DD + i) * HIDN + c0 + c] = __float2half_rn(acc);
    }
}

// ---------------- f16 TC GEMM v6: half in, BK=64, pure-copy staging ----------------
// mode 0: plain fp32 out [m, HIDN]; mode 3: Q-featurize; mode 4: K-featurize+ck; mode 5: V->half [d][l]
template<int BM>
__global__ void __launch_bounds__(256) gemm_tc(
    const __half* __restrict__ X0, const __half* __restrict__ Wm0, const float* __restrict__ B0, float* __restrict__ O0, int md0,
    const __half* __restrict__ X1, const __half* __restrict__ Wm1, const float* __restrict__ B1, float* __restrict__ O1, int md1,
    const __half* __restrict__ X2, const __half* __restrict__ Wm2, const float* __restrict__ B2, float* __restrict__ O2, int md2,
    const float* __restrict__ vw)
{
    const int BK = 64;
    const int NIT = HIDN / BK;        // 8
    const int NT = (BM == 64) ? 4 : 2;
    const int XU4 = BM / 32;          // uint4 per thread for X (2 or 1)
    int z = blockIdx.z;
    const __half* X = z == 0 ? X0  : (z == 1 ? X1  : X2);
    const __half* W = z == 0 ? Wm0 : (z == 1 ? Wm1 : Wm2);
    const float* Bi = z == 0 ? B0  : (z == 1 ? B1  : B2);
    float*        O = z == 0 ? O0  : (z == 1 ? O1  : O2);
    int        mode = z == 0 ? md0 : (z == 1 ? md1 : md2);

    __shared__ union {
        struct { unsigned X[BM * 36]; unsigned W[64 * 36]; } st;
        float out[BM * 68];
    } sm;

    int tid = threadIdx.x;
    int lane = tid & 31;
    int warp = tid >> 5;
    int warp_m = (BM == 64) ? (warp & 3) * 16 : (warp & 1) * 16;
    int warp_n = (BM == 64) ? (warp >> 2) * 32 : (warp >> 1) * 16;
    int gr = lane >> 2;
    int tg = lane & 3;
    int m0 = blockIdx.y * BM, n0 = blockIdx.x * 64;

    int xr = tid >> 3;                // 0..31 row
    int xc = tid & 7;                 // 0..7 uint4 col (8 halves each)

    float acc[NT][4];
#pragma unroll
    for (int nt = 0; nt < NT; nt++)
#pragma unroll
        for (int i = 0; i < 4; i++) acc[nt][i] = 0.f;

    uint4 px[XU4], pw[2];
#pragma unroll
    for (int i = 0; i < XU4; i++)
        px[i] = *(const uint4*)&X[(size_t)(m0 + xr + i * 32) * HIDN + xc * 8];
#pragma unroll
    for (int i = 0; i < 2; i++)
        pw[i] = *(const uint4*)&W[(size_t)(n0 + xr + i * 32) * HIDN + xc * 8];

    for (int it = 0; it < NIT; it++) {
#pragma unroll
        for (int i = 0; i < XU4; i++)
            *(uint4*)&sm.st.X[(xr + i * 32) * 36 + xc * 4] = px[i];
#pragma unroll
        for (int i = 0; i < 2; i++)
            *(uint4*)&sm.st.W[(xr + i * 32) * 36 + xc * 4] = pw[i];
        __syncthreads();
        if (it + 1 < NIT) {
            int kk = (it + 1) * BK;
#pragma unroll
            for (int i = 0; i < XU4; i++)
                px[i] = *(const uint4*)&X[(size_t)(m0 + xr + i * 32) * HIDN + kk + xc * 8];
#pragma unroll
            for (int i = 0; i < 2; i++)
                pw[i] = *(const uint4*)&W[(size_t)(n0 + xr + i * 32) * HIDN + kk + xc * 8];
        }
#pragma unroll
        for (int s = 0; s < 4; s++) {
            int kb = s * 8;
            unsigned a[4], b[NT][2];
            a[0] = sm.st.X[(warp_m + gr    ) * 36 + kb + tg];
            a[1] = sm.st.X[(warp_m + gr + 8) * 36 + kb + tg];
            a[2] = sm.st.X[(warp_m + gr    ) * 36 + kb + 4 + tg];
            a[3] = sm.st.X[(warp_m + gr + 8) * 36 + kb + 4 + tg];
#pragma unroll
            for (int nt = 0; nt < NT; nt++) {
                int rn = warp_n + nt * 8 + gr;
                b[nt][0] = sm.st.W[rn * 36 + kb + tg];
                b[nt][1] = sm.st.W[rn * 36 + kb + 4 + tg];
            }
#pragma unroll
            for (int nt = 0; nt < NT; nt++)
                mma_f16(acc[nt], a, b[nt]);
        }
        __syncthreads();
    }

#pragma unroll
    for (int nt = 0; nt < NT; nt++) {
        int col = warp_n + nt * 8 + 2 * tg;
        sm.out[(warp_m + gr    ) * 68 + col    ] = acc[nt][0];
        sm.out[(warp_m + gr    ) * 68 + col + 1] = acc[nt][1];
        sm.out[(warp_m + gr + 8) * 68 + col    ] = acc[nt][2];
        sm.out[(warp_m + gr + 8) * 68 + col + 1] = acc[nt][3];
    }
    __syncthreads();

    int b_ = m0 / LL, l0 = m0 - b_ * LL;
    int h = n0 >> 6;
    int bh = b_ * HH + h;

    if (mode == 0) {
#pragma unroll
        for (int i = 0; i < BM / 16; i++) {
            int idx = tid + i * 256;
            int r = idx >> 4, c4 = idx & 15;
            float4 v = *(float4*)&sm.out[r * 68 + c4 * 4];
            float4 b4 = *(const float4*)&Bi[n0 + c4 * 4];
            v.x += b4.x; v.y += b4.y; v.z += b4.z; v.w += b4.w;
            *(float4*)&O[(m0 + r) * HIDN + n0 + c4 * 4] = v;
        }
    } else if (mode == 3 || mode == 4) {
        __half* Fdst = (mode == 3 ? g_FQ : g_FK) + (size_t)(bh * LL + l0) * FD;
#pragma unroll
        for (int i = 0; i < BM / 16; i++) {
            int idx = tid + i * 256;
            int r = idx >> 4, c4 = idx & 15;
            int d0 = c4 * 4;
            float4 v = *(float4*)&sm.out[r * 68 + d0];
            float4 b4 = *(const float4*)&Bi[n0 + d0];
            float t0 = tanh_ap(v.x + b4.x), t1 = tanh_ap(v.y + b4.y);
            float t2 = tanh_ap(v.z + b4.z), t3 = tanh_ap(v.w + b4.w);
            float w0 = __ldg(&vw[d0]), w1 = __ldg(&vw[d0 + 1]);
            float w2 = __ldg(&vw[d0 + 2]), w3 = __ldg(&vw[d0 + 3]);
            __half* row = Fdst + (size_t)r * FD;
            if (mode == 3) {
                // FQ = [ta^2, vw*ta]
                *(__half2*)&row[0*64 + d0    ] = __floats2half2_rn(t0*t0, t1*t1);
                *(__half2*)&row[0*64 + d0 + 2] = __floats2half2_rn(t2*t2, t3*t3);
                *(__half2*)&row[1*64 + d0    ] = __floats2half2_rn(w0*t0, w1*t1);
                *(__half2*)&row[1*64 + d0 + 2] = __floats2half2_rn(w2*t2, w3*t3);
            } else {
                // FK = [-vw*tb, -tb^2]
                *(__half2*)&row[0*64 + d0    ] = __floats2half2_rn(-w0*t0, -w1*t1);
                *(__half2*)&row[0*64 + d0 + 2] = __floats2half2_rn(-w2*t2, -w3*t3);
                *(__half2*)&row[1*64 + d0    ] = __floats2half2_rn(-t0*t0, -t1*t1);
                *(__half2*)&row[1*64 + d0 + 2] = __floats2half2_rn(-t2*t2, -t3*t3);
                float cp = w0*t0 + w1*t1 + w2*t2 + w3*t3;
#pragma unroll
                for (int o = 1; o < 16; o <<= 1) cp += __shfl_xor_sync(0xffffffffu, cp, o);
                if ((tid & 15) == 0) g_ck[bh * LL + l0 + r] = cp;
            }
        }
    } else {
        __half* base = g_Vh + (size_t)bh * DD * LL;
#pragma unroll
        for (int i = 0; i < BM / 16; i++) {
            int idx = tid + i * 256;
            int d = idx >> 4, l4 = idx & 15;
            float bd = __ldg(&Bi[n0 + d]);
            float v0 = sm.out[(l4 * 4 + 0) * 68 + d] + bd;
            float v1 = sm.out[(l4 * 4 + 1) * 68 + d] + bd;
            float v2 = sm.out[(l4 * 4 + 2) * 68 + d] + bd;
            float v3 = sm.out[(l4 * 4 + 3) * 68 + d] + bd;
            *(__half2*)&base[d * LL + l0 + l4 * 4    ] = __floats2half2_rn(v0, v1);
            *(__half2*)&base[d * LL + l0 + l4 * 4 + 2] = __floats2half2_rn(v2, v3);
        }
    }
}

// ---------------- attention: E = FQ@FK^T + ck -> softmax -> X = P@V (f16 MMA) ----
#define LLP 392
#define FDP 136
#define VHS 72
#define EOFF  0
#define FQOFF (32*LLP*4)                       // 50176
#define FKOFF (FQOFF + 32*FDP*2)               // 58880
#define VHOFF FKOFF
#define CKOFF (FKOFF + 64*FDP*2)               // 76288
#define MOFF  (CKOFF + LL*4)                   // 77824
#define SMEM_ATTN (MOFF + LL*4)                // 79360

__global__ void __launch_bounds__(256) attn_fused(
    const int* __restrict__ mask, float* __restrict__ attn)
{
    extern __shared__ char smraw[];
    float*  E  = (float*) (smraw + EOFF);   // [32][LLP]
    __half* FQ = (__half*)(smraw + FQOFF);  // [32][FDP]
    __half* FK = (__half*)(smraw + FKOFF);  // [64][FDP]
    __half* Vh = (__half*)(smraw + VHOFF);  // [64][VHS]
    float*  CK = (float*) (smraw + CKOFF);
    int*    M  = (int*)   (smraw + MOFF);

    int tid = threadIdx.x;
    int lane = tid & 31, warp = tid >> 5;
    int wm = (warp & 1) * 16;
    int wn = (warp >> 1) * 16;
    int gr = lane >> 2, tg = lane & 3;
    int bh = blockIdx.y, b = bh >> 3, h = bh & 7;
    int q0 = blockIdx.x * 32;

    for (int j = tid; j < LL; j += 256) { M[j] = mask[b * LL + j]; CK[j] = g_ck[bh * LL + j]; }
    {
        const unsigned* s32 = (const unsigned*)(g_FQ + (size_t)(bh * LL + q0) * FD);
#pragma unroll
        for (int i = 0; i < 8; i++) {
            int idx = tid + i * 256;
            int r = idx >> 6, c2 = idx & 63;
            *(unsigned*)&FQ[r * FDP + c2 * 2] = s32[r * 64 + c2];
        }
    }

    // ---- E phase: register double-buffered FK chunks ----
    const uint4* fksrc = (const uint4*)(g_FK + (size_t)bh * LL * FD);
    uint4 pfk[4];
#pragma unroll
    for (int i = 0; i < 4; i++) pfk[i] = fksrc[tid + i * 256];

    for (int c = 0; c < 6; c++) {
        __syncthreads();
#pragma unroll
        for (int i = 0; i < 4; i++) {
            int flat = tid + i * 256;
            int r = flat >> 4, c16 = flat & 15;
            *(uint4*)&FK[r * FDP + c16 * 8] = pfk[i];
        }
        __syncthreads();
        if (c < 6 - 1) {
            const uint4* nsrc = fksrc + (c + 1) * 1024;
#pragma unroll
            for (int i = 0; i < 4; i++) pfk[i] = nsrc[tid + i * 256];
        }
        float eacc[2][4];
#pragma unroll
        for (int nt = 0; nt < 2; nt++)
#pragma unroll
            for (int i = 0; i < 4; i++) eacc[nt][i] = 0.f;
#pragma unroll
        for (int ks = 0; ks < FD / 16; ks++) {
            int k0 = ks * 16;
            unsigned a[4], bf[2][2];
            a[0] = *(const unsigned*)&FQ[(wm + gr    ) * FDP + k0 + 2 * tg];
            a[1] = *(const unsigned*)&FQ[(wm + gr + 8) * FDP + k0 + 2 * tg];
            a[2] = *(const unsigned*)&FQ[(wm + gr    ) * FDP + k0 + 2 * tg + 8];
            a[3] = *(const unsigned*)&FQ[(wm + gr + 8) * FDP + k0 + 2 * tg + 8];
#pragma unroll
            for (int nt = 0; nt < 2; nt++) {
                int rn = wn + nt * 8 + gr;
                bf[nt][0] = *(const unsigned*)&FK[rn * FDP + k0 + 2 * tg];
                bf[nt][1] = *(const unsigned*)&FK[rn * FDP + k0 + 2 * tg + 8];
            }
            mma_f16(eacc[0], a, bf[0]);
            mma_f16(eacc[1], a, bf[1]);
        }
#pragma unroll
        for (int nt = 0; nt < 2; nt++) {
            int col = c * 64 + wn + nt * 8 + 2 * tg;
            *(float2*)&E[(wm + gr    ) * LLP + col] = make_float2(eacc[nt][0], eacc[nt][1]);
            *(float2*)&E[(wm + gr + 8) * LLP + col] = make_float2(eacc[nt][2], eacc[nt][3]);
        }
    }
    __syncthreads();

    // ---- softmax ----
    {
        int row = tid >> 3, lx = tid & 7;
        float mx = -3.0e38f;
        for (int i = 0; i < 48; i++) {
            int j = lx + i * 8;
            float e = E[row * LLP + j] + CK[j];
            if (M[j] == 0) e = -1e10f;
            E[row * LLP + j] = e;
            mx = fmaxf(mx, e);
        }
#pragma unroll
        for (int o = 4; o > 0; o >>= 1) mx = fmaxf(mx, __shfl_xor_sync(0xffffffffu, mx, o));
        float sum = 0.f;
        for (int i = 0; i < 48; i++) {
            int j = lx + i * 8;
            float p = __expf(E[row * LLP + j] - mx);
            sum += p;
            E[row * LLP + j] = p;
        }
#pragma unroll
        for (int o = 4; o > 0; o >>= 1) sum += __shfl_xor_sync(0xffffffffu, sum, o);
        float inv = __frcp_rn(sum);
        for (int i = 0; i < 48; i++) E[row * LLP + lx + i * 8] *= inv;
    }
    __syncthreads();

    // ---- prefetch Vh chunk 0 (overlaps attn gmem store) ----
    const uint4* vsrc = (const uint4*)(g_Vh + (size_t)bh * DD * LL);
    int vd = tid >> 3, vc8 = tid & 7;
    uint4 pv[2];
#pragma unroll
    for (int i = 0; i < 2; i++) pv[i] = vsrc[(vd + i * 32) * 48 + vc8];

    // coalesced attn store (no integer division)
    {
        float* dst = attn + (size_t)(bh * LL + q0) * LL;
        int r = 0, j = tid;
        if (j >= LL) { j -= LL; r = 1; }
#pragma unroll
        for (int it = 0; it < 48; it++) {
            dst[r * LL + j] = E[r * LLP + j];
            j += 256;
            if (j >= LL) { j -= LL; r++; }
        }
    }

    // ---- AV phase: register double-buffered Vh chunks ----
    float xacc[2][4];
#pragma unroll
    for (int nt = 0; nt < 2; nt++)
#pragma unroll
        for (int i = 0; i < 4; i++) xacc[nt][i] = 0.f;

    for (int c = 0; c < 6; c++) {
        __syncthreads();
#pragma unroll
        for (int i = 0; i < 2; i++) {
            int d = vd + i * 32;
            *(uint4*)&Vh[d * VHS + vc8 * 8] = pv[i];
        }
        __syncthreads();
        if (c < 6 - 1) {
#pragma unroll
            for (int i = 0; i < 2; i++) pv[i] = vsrc[(vd + i * 32) * 48 + (c + 1) * 8 + vc8];
        }
#pragma unroll
        for (int ks = 0; ks < 4; ks++) {
            int kg = c * 64 + ks * 16;
            unsigned a[4], bf[2][2];
            float2 p0 = *(const float2*)&E[(wm + gr    ) * LLP + kg + 2 * tg];
            float2 p1 = *(const float2*)&E[(wm + gr + 8) * LLP + kg + 2 * tg];
            float2 p2 = *(const float2*)&E[(wm + gr    ) * LLP + kg + 2 * tg + 8];
            float2 p3 = *(const float2*)&E[(wm + gr + 8) * LLP + kg + 2 * tg + 8];
            a[0] = h2u(__floats2half2_rn(p0.x, p0.y));
            a[1] = h2u(__floats2half2_rn(p1.x, p1.y));
            a[2] = h2u(__floats2half2_rn(p2.x, p2.y));
            a[3] = h2u(__floats2half2_rn(p3.x, p3.y));
            int kl = ks * 16 + 2 * tg;
#pragma unroll
            for (int nt = 0; nt < 2; nt++) {
                int rn = wn + nt * 8 + gr;
                bf[nt][0] = *(const unsigned*)&Vh[rn * VHS + kl];
                bf[nt][1] = *(const unsigned*)&Vh[rn * VHS + kl + 8];
            }
            mma_f16(xacc[0], a, bf[0]);
            mma_f16(xacc[1], a, bf[1]);
        }
    }

    // X store as half (feeds out-proj gemm directly)
    {
        int q = q0 + wm + gr;
#pragma unroll
        for (int nt = 0; nt < 2; nt++) {
            int d = h * DD + wn + nt * 8 + 2 * tg;
            *(__half2*)&g_Xh[(size_t)(b * LL + q    ) * HIDN + d] = __floats2half2_rn(xacc[nt][0], xacc[nt][1]);
            *(__half2*)&g_Xh[(size_t)(b * LL + q + 8) * HIDN + d] = __floats2half2_rn(xacc[nt][2], xacc[nt][3]);
        }
    }
}

extern "C" void kernel_launch(void* const* d_in, const int* in_sizes, int n_in,
                              void* d_out, int out_size)
{
    const float* query = (const float*)d_in[0];
    const float* key_  = (const float*)d_in[1];
    const float* value = (const float*)d_in[2];
    const int*   mask  = (const int*)  d_in[3];
    const float* Wq = (const float*)d_in[4];
    const float* bq = (const float*)d_in[5];
    const float* Wk = (const float*)d_in[6];
    const float* bk = (const float*)d_in[7];
    const float* Wv = (const float*)d_in[8];
    const float* bv = (const float*)d_in[9];
    const float* Wo = (const float*)d_in[10];
    const float* bo = (const float*)d_in[11];
    const float* W1 = (const float*)d_in[12];
    const float* b1 = (const float*)d_in[13];
    const float* W2 = (const float*)d_in[14];
    const float* b2 = (const float*)d_in[15];
    const float* vw = (const float*)d_in[16];
    (void)d_in[17];
    (void)in_sizes; (void)n_in;

    float* out = (float*)d_out;

    __half *gQh, *gKh, *gVin, *gWvh, *gWoh, *gWfqh, *gWfkh, *gXh;
    float *gA, *gbfq, *gbfk;
    cudaGetSymbolAddress((void**)&gQh,   g_Qh);
    cudaGetSymbolAddress((void**)&gKh,   g_Kh2);
    cudaGetSymbolAddress((void**)&gVin,  g_Vin);
    cudaGetSymbolAddress((void**)&gWvh,  g_Wvh);
    cudaGetSymbolAddress((void**)&gWoh,  g_Woh);
    cudaGetSymbolAddress((void**)&gWfqh, g_Wfqh);
    cudaGetSymbolAddress((void**)&gWfkh, g_Wfkh);
    cudaGetSymbolAddress((void**)&gXh,   g_Xh);
    cudaGetSymbolAddress((void**)&gA,    g_attn);
    cudaGetSymbolAddress((void**)&gbfq,  g_bfq);
    cudaGetSymbolAddress((void**)&gbfk,  g_bfk);

    float* attn_dst = (out_size >= X_ELEMS + A_ELEMS) ? (out + X_ELEMS) : gA;

    cudaFuncSetAttribute(attn_fused, cudaFuncAttributeMaxDynamicSharedMemorySize, SMEM_ATTN);

    // 0) fp32 -> f16 inputs/weights (384x5 blocks)
    cvt_half_k<<<dim3(X_ELEMS / 1024, 5), 256>>>(query, key_, value, Wv, Wo);

    // 1) fuse W1@Wq and W2@Wk -> half (128 blocks)
    prep_fuse<<<dim3(HH, 2, HIDN / 64), 256>>>(W1, b1, W2, b2, Wq, bq, Wk, bk);

    // 2) projections + featurization — f16-in TC GEMM, 288 blocks (BM=64)
    gemm_tc<64><<<dim3(HIDN / 64, MROWS / 64, 3), 256>>>(
        gQh,  gWfqh, gbfq, nullptr, 3,
        gKh,  gWfkh, gbfk, nullptr, 4,
        gVin, gWvh,  bv,   nullptr, 5,
        vw);

    // 3) attention: E-mma + softmax + AV-mma, double-buffered (192 blocks)
    attn_fused<<<dim3(LL / 32, BH), 256, SMEM_ATTN>>>(mask, attn_dst);

    // 4) output projection — f16-in TC GEMM, 192 blocks (BM=32)
    gemm_tc<32><<<dim3(HIDN / 64, MROWS / 32, 1), 256>>>(
        gXh, gWoh, bo, out, 0,
        gXh, gWoh, bo, out, 0,
        gXh, gWoh, bo, out, 0,
        vw);
}